// round 15
// baseline (speedup 1.0000x reference)
#include <cuda_runtime.h>
#include <cstdint>

// ConditionalODE: fused MLP forward + exact 2-tangent JVP divergence.
// Round 15: 2 CTAs/SM (8 tokens per CTA, 24 state rows, 114688 B smem each)
// so barrier/LN bubbles of one CTA are filled by the other CTA's GEMM warps.
// GEMM tile: 4 rowgroups x 6 rows, 128 colgroups x 4 cols (2 b64 accs/row),
// float2 A reloads -> ~58 regs under the 64-reg 2-CTA cap.
// FFMA2 packed fp32; 4k-row weight panels, one barrier per panel;
// layer-0 cond@W0 hoisted per-batch (g_condW).

#define NTOK 131072
#define EPS  1e-5f

__device__ float g_condW[2048 * 512];   // per-batch cond @ W0[4:132]  (4 MB)

__device__ __forceinline__ void cp_async16(float* s, const float* g) {
    unsigned u = (unsigned)__cvta_generic_to_shared(s);
    asm volatile("cp.async.cg.shared.global [%0], [%1], 16;\n" :: "r"(u), "l"(g) : "memory");
}
__device__ __forceinline__ void cp_commit() {
    asm volatile("cp.async.commit_group;\n" ::: "memory");
}
__device__ __forceinline__ void cp_wait0() {
    asm volatile("cp.async.wait_group 0;\n" ::: "memory");
}

// ---- packed fp32 helpers (sm_103a f32x2 pipe) ----
__device__ __forceinline__ unsigned long long splat2(float a) {
    unsigned long long r;
    unsigned ai = __float_as_uint(a);
    asm("mov.b64 %0, {%1, %1};" : "=l"(r) : "r"(ai));
    return r;
}
__device__ __forceinline__ void ffma2(unsigned long long& d,
                                      unsigned long long a, unsigned long long b) {
    asm("fma.rn.f32x2 %0, %1, %2, %0;" : "+l"(d) : "l"(a), "l"(b));
}

// GEMM: sOut[24][512] = sIn[24][512] @ Wb[512][512] using FFMA2.
// 512 threads: rg = tid>>7 (0..3) owns rows rg*6..rg*6+5 (warp-uniform ->
// A loads are LDS broadcasts); cg = tid&127 owns cols cg*4..cg*4+3 (2 b64).
// Weight k-panels (4x512) double-buffered via cp.async; ONE barrier per panel.
__device__ __forceinline__ void gemm512(
    const float* __restrict__ Wb,
    const float* __restrict__ sIn, float* __restrict__ sW, float* __restrict__ sOut)
{
    const int tid = threadIdx.x;
    const int rowBase = (tid >> 7) * 6;
    const int c0 = (tid & 127) * 4;

    unsigned long long acc[6][2];
#pragma unroll
    for (int j = 0; j < 6; ++j) { acc[j][0] = 0ull; acc[j][1] = 0ull; }

    // staging: 512 threads x 16B: row = tid>>7 (0..3), col = (tid&127)*4
    const int srow = tid >> 7;
    const int scol = (tid & 127) * 4;

    // prologue: stage panel 0 into buffer 0
    cp_async16(sW + srow*512 + scol, Wb + srow*512 + scol);
    cp_commit();

#pragma unroll 1
    for (int p = 0; p < 128; ++p) {
        float* cb = sW + (p & 1) * 2048;
        cp_wait0();          // own part of panel p done
        __syncthreads();     // all parts of p visible; readers of p-1 done
        if (p + 1 < 128) {
            // buffer (p+1)&1 held panel p-1: safe to overwrite now
            float* nb = sW + ((p + 1) & 1) * 2048;
            const float* src = Wb + (p + 1) * 2048;
            cp_async16(nb + srow*512 + scol, src + srow*512 + scol);
            cp_commit();
        }
        const int kg = p << 2;
#pragma unroll
        for (int kk = 0; kk < 4; kk += 2) {
            float2 a[6];
#pragma unroll
            for (int j = 0; j < 6; ++j)
                a[j] = *(const float2*)&sIn[(rowBase + j)*512 + kg + kk];
#pragma unroll
            for (int kq = 0; kq < 2; ++kq) {
                ulonglong2 bv = *(const ulonglong2*)&cb[(kk + kq)*512 + c0];
#pragma unroll
                for (int j = 0; j < 6; ++j) {
                    unsigned long long a2 = splat2(kq ? a[j].y : a[j].x);
                    ffma2(acc[j][0], a2, bv.x);
                    ffma2(acc[j][1], a2, bv.y);
                }
            }
        }
        // no trailing barrier: next iteration's top barrier gates reuse
    }
#pragma unroll
    for (int j = 0; j < 6; ++j)
        *(ulonglong2*)&sOut[(rowBase + j)*512 + c0] = make_ulonglong2(acc[j][0], acc[j][1]);
}

// Fused bias(te/pos) + LayerNorm + softplus, with JVP for two tangents.
// Warps 0..7: one token each. In-place on buf (rows: 0-7 x, 8-15 u0, 16-23 u1).
__device__ __forceinline__ void elementwise_ln(
    float* __restrict__ buf,
    const float* __restrict__ bvec, const float* __restrict__ gvec,
    const float* __restrict__ bevec, const float* __restrict__ Wfull,
    float tval, int tok0)
{
    const int i = threadIdx.x >> 5;
    if (i >= 8) return;
    const int l = threadIdx.x & 31;
    const float pos = (float)(((tok0 + i) & 63) + 1) * (1.f/64.f);
    float* xr  = buf + i*512;
    float* u0r = buf + (8+i)*512;
    float* u1r = buf + (16+i)*512;

    float s1=0.f,s2=0.f,s3=0.f,s4=0.f,s5=0.f,s6=0.f;
    for (int k = l; k < 512; k += 32) {
        float cv = __ldg(&bvec[k]) + tval*__ldg(&Wfull[k]) + pos*__ldg(&Wfull[512+k]);
        float x = xr[k] + cv;
        xr[k] = x;
        float u0 = u0r[k], u1 = u1r[k];
        s1 += x;     s2 += x*x;
        s3 += u0;    s4 += x*u0;
        s5 += u1;    s6 += x*u1;
    }
#pragma unroll
    for (int o = 16; o > 0; o >>= 1) {
        s1 += __shfl_xor_sync(0xffffffffu, s1, o);
        s2 += __shfl_xor_sync(0xffffffffu, s2, o);
        s3 += __shfl_xor_sync(0xffffffffu, s3, o);
        s4 += __shfl_xor_sync(0xffffffffu, s4, o);
        s5 += __shfl_xor_sync(0xffffffffu, s5, o);
        s6 += __shfl_xor_sync(0xffffffffu, s6, o);
    }
    const float inv = 1.f/512.f;
    float mu   = s1*inv;
    float var  = s2*inv - mu*mu;
    float r    = rsqrtf(var + EPS);
    float mu0  = s3*inv, mu1 = s5*inv;
    float cov0 = s4*inv - mu*mu0;
    float cov1 = s6*inv - mu*mu1;
    float r3c0 = r*r*r*cov0;
    float r3c1 = r*r*r*cov1;
    for (int k = l; k < 512; k += 32) {
        float x  = xr[k];
        float xc = x - mu;
        float gg = __ldg(&gvec[k]);
        float y  = fmaf(xc*r, gg, __ldg(&bevec[k]));
        float e  = __expf(-fabsf(y));
        float sp = fmaxf(y, 0.f) + log1pf(e);
        float sg = (y >= 0.f) ? (1.f/(1.f+e)) : (e/(1.f+e));
        float du0 = sg * gg * (r*(u0r[k]-mu0) - xc*r3c0);
        float du1 = sg * gg * (r*(u1r[k]-mu1) - xc*r3c1);
        xr[k]  = sp;
        u0r[k] = du0;
        u1r[k] = du1;
    }
}

// Pre-kernel: g_condW[b][n] = sum_c cond[b][c] * W0[(4+c)*512+n].
__global__ void __launch_bounds__(512) condw_kernel(
    const float* __restrict__ cond, const float* __restrict__ W0)
{
    __shared__ float sc[8 * 128];
    const int n  = threadIdx.x;
    const int bb = blockIdx.x * 8;
    for (int idx = n; idx < 8*128; idx += 512) sc[idx] = cond[bb*128 + idx];
    __syncthreads();
    float acc[8];
#pragma unroll
    for (int j = 0; j < 8; ++j) acc[j] = 0.f;
    for (int c = 0; c < 128; ++c) {
        float w = W0[(4 + c)*512 + n];
#pragma unroll
        for (int j = 0; j < 8; ++j) acc[j] = fmaf(sc[j*128 + c], w, acc[j]);
    }
#pragma unroll
    for (int j = 0; j < 8; ++j) g_condW[(bb + j)*512 + n] = acc[j];
}

__global__ void __launch_bounds__(512, 2) ode_kernel(
    const float* __restrict__ tptr, const float* __restrict__ z,
    const float* __restrict__ cond,
    const float* __restrict__ W0, const float* __restrict__ b0,
    const float* __restrict__ g0, const float* __restrict__ be0,
    const float* __restrict__ W1, const float* __restrict__ b1,
    const float* __restrict__ g1, const float* __restrict__ be1,
    const float* __restrict__ W2, const float* __restrict__ b2,
    const float* __restrict__ g2, const float* __restrict__ be2,
    const float* __restrict__ W3, const float* __restrict__ b3,
    float* __restrict__ out)
{
    extern __shared__ float smem[];
    float* sA = smem;            // 24x512
    float* sB = smem + 12288;    // 24x512
    float* sW = smem + 24576;    // 2 x (4x512) weight panels
    const int tid  = threadIdx.x;
    const int tok0 = blockIdx.x * 8;
    const float tval = tptr[0];

    // ---- Layer 0 (algebraic): primal = z0*W0r2 + z1*W0r3 + condW; u0=W0r2, u1=W0r3
    if (tid < 16) sW[tid] = z[tok0*2 + tid];
    __syncthreads();
    {
        const int n = tid;
        float w2  = W0[1024 + n];
        float w3  = W0[1536 + n];
        float cwv = g_condW[(tok0 >> 6)*512 + n];
#pragma unroll
        for (int i = 0; i < 8; ++i) {
            float z0 = sW[i*2], z1 = sW[i*2 + 1];
            sB[i*512 + n]        = fmaf(z0, w2, fmaf(z1, w3, cwv));
            sB[(8 + i)*512 + n]  = w2;
            sB[(16 + i)*512 + n] = w3;
        }
    }
    __syncthreads();
    elementwise_ln(sB, b0, g0, be0, W0, tval, tok0);
    __syncthreads();

    // ---- Layer 1
    gemm512(W1 + 1024, sB, sW, sA);
    __syncthreads();
    elementwise_ln(sA, b1, g1, be1, W1, tval, tok0);
    __syncthreads();

    // ---- Layer 2
    gemm512(W2 + 1024, sA, sW, sB);
    __syncthreads();
    elementwise_ln(sB, b2, g2, be2, W2, tval, tok0);
    __syncthreads();

    // ---- Layer 3: per-token dots (warps 0..7, one token each)
    {
        const int i = tid >> 5, l = tid & 31;
        if (i < 8) {
            const int token = tok0 + i;
            const float pos = (float)((token & 63) + 1) * (1.f/64.f);
            const float* xr  = sB + i*512;
            const float* u0r = sB + (8+i)*512;
            const float* u1r = sB + (16+i)*512;
            float a0=0.f, a1=0.f, d0=0.f, d1=0.f;
            for (int k = l; k < 512; k += 32) {
                float2 wv = *(const float2*)&W3[(2+k)*2];
                float h = xr[k];
                a0 = fmaf(h, wv.x, a0);
                a1 = fmaf(h, wv.y, a1);
                d0 = fmaf(u0r[k], wv.x, d0);
                d1 = fmaf(u1r[k], wv.y, d1);
            }
#pragma unroll
            for (int o = 16; o > 0; o >>= 1) {
                a0 += __shfl_xor_sync(0xffffffffu, a0, o);
                a1 += __shfl_xor_sync(0xffffffffu, a1, o);
                d0 += __shfl_xor_sync(0xffffffffu, d0, o);
                d1 += __shfl_xor_sync(0xffffffffu, d1, o);
            }
            if (l == 0) {
                out[token*2 + 0] = a0 + b3[0] + tval*W3[0] + pos*W3[2];
                out[token*2 + 1] = a1 + b3[1] + tval*W3[1] + pos*W3[3];
                out[2*NTOK + token] = -(d0 + d1);
            }
        }
    }
}

extern "C" void kernel_launch(void* const* d_in, const int* in_sizes, int n_in,
                              void* d_out, int out_size)
{
    const float* t    = (const float*)d_in[0];
    const float* z    = (const float*)d_in[1];
    const float* cond = (const float*)d_in[2];
    const float* W0   = (const float*)d_in[3];
    const float* b0   = (const float*)d_in[4];
    const float* g0   = (const float*)d_in[5];
    const float* be0  = (const float*)d_in[6];
    const float* W1   = (const float*)d_in[7];
    const float* b1   = (const float*)d_in[8];
    const float* g1   = (const float*)d_in[9];
    const float* be1  = (const float*)d_in[10];
    const float* W2   = (const float*)d_in[11];
    const float* b2   = (const float*)d_in[12];
    const float* g2   = (const float*)d_in[13];
    const float* be2  = (const float*)d_in[14];
    const float* W3   = (const float*)d_in[15];
    const float* b3   = (const float*)d_in[16];
    float* out = (float*)d_out;

    condw_kernel<<<256, 512>>>(cond, W0);

    const size_t smem_bytes = 28672 * sizeof(float);  // 114688 B per CTA
    cudaFuncSetAttribute(ode_kernel, cudaFuncAttributeMaxDynamicSharedMemorySize,
                         (int)smem_bytes);
    ode_kernel<<<NTOK/8, 512, smem_bytes>>>(
        t, z, cond, W0, b0, g0, be0, W1, b1, g1, be1,
        W2, b2, g2, be2, W3, b3, out);
}

// round 17
// speedup vs baseline: 2.5049x; 2.5049x over previous
#include <cuda_runtime.h>
#include <cuda_bf16.h>
#include <cstdint>

// ConditionalODE: fused MLP forward + exact 2-tangent JVP divergence.
// Round 17: tcgen05 is unavailable (harness ptxas targets sm_103, not
// sm_103a). Use base-feature tensor path instead: mma.sync.m16n8k16 bf16
// (HMMA). Unfused pipeline:
//   condw  : per-batch cond @ W0[4:132]                     (fp32)
//   prep   : W1/W2 rows 2..513 -> transposed bf16 hi/lo planes
//   ln0    : algebraic layer0 + LN + softplus JVP -> X planes (bf16 hi/lo)
//   gemm x2: Y[393216,512] = X @ W, 3-product hi/lo split
//            (Ah*Bh + Ah*Bl + Al*Bh), fp32 accum in registers
//   ln_mid : LN1 on Y -> X planes
//   final  : LN2 on Y + layer-3 dots -> out

#define NTOK 131072
#define ROWS (3 * NTOK)          // 393216 GEMM rows
#define EPS  1e-5f

// ---------------- scratch (__device__ globals; no allocations) -------------
__device__ float         g_condW[2048 * 512];                  // 4 MB
__device__ __nv_bfloat16 g_Xh[(size_t)ROWS * 512];             // 402 MB
__device__ __nv_bfloat16 g_Xl[(size_t)ROWS * 512];             // 402 MB
__device__ float         g_Y[(size_t)ROWS * 512];              // 805 MB
__device__ __nv_bfloat16 g_Wt[4][512 * 512];                   // W1h,W1l,W2h,W2l

// ---------------- helpers ---------------------------------------------------
__device__ __forceinline__ void cpa16(uint32_t s, const void* g) {
    asm volatile("cp.async.cg.shared.global [%0], [%1], 16;\n" :: "r"(s), "l"(g) : "memory");
}
__device__ __forceinline__ uint32_t smem_u32(const void* p) {
    uint32_t a;
    asm("{ .reg .u64 t; cvta.to.shared.u64 t, %1; cvt.u32.u64 %0, t; }"
        : "=r"(a) : "l"(p));
    return a;
}
__device__ __forceinline__ void mma_bf16(float* c, const uint32_t* a, const uint32_t* b) {
    asm volatile(
        "mma.sync.aligned.m16n8k16.row.col.f32.bf16.bf16.f32 "
        "{%0,%1,%2,%3}, {%4,%5,%6,%7}, {%8,%9}, {%0,%1,%2,%3};"
        : "+f"(c[0]), "+f"(c[1]), "+f"(c[2]), "+f"(c[3])
        : "r"(a[0]), "r"(a[1]), "r"(a[2]), "r"(a[3]), "r"(b[0]), "r"(b[1]));
}

// ---------------- GEMM ------------------------------------------------------
// Y[m0:+128, n0:+128] = X @ Wt^T with bf16 hi/lo 3-product split.
// 256 threads = 8 warps: wm = wid&3 (rows wm*32), wn = wid>>2 (cols wn*64).
// Smem stage (40960 B): Ah[128][40] Al[128][40] Bh[128][40] Bl[128][40]
// (rows padded 32->40 bf16: word idx = row*20 + tg -> conflict-free frags).
// 3-stage cp.async pipeline over 16 k-chunks of 32.
#define STG_BYTES 40960
#define PLANE_BYTES 10240

__device__ __forceinline__ void g_load_stage(
    uint32_t sb, int kc, int m0, int n0,
    const __nv_bfloat16* __restrict__ Wh, const __nv_bfloat16* __restrict__ Wl,
    int tid)
{
    // A planes: 1024 chunks of 16B (2 planes x 128 rows x 4 chunks)
#pragma unroll
    for (int i = 0; i < 4; ++i) {
        int cid = tid + i * 256;            // 0..1023
        int plane = cid >> 9;               // 0:hi 1:lo
        int r     = (cid & 511) >> 2;       // 0..127
        int ch    = cid & 3;                // 0..3 (16B chunks)
        uint32_t d = sb + plane * PLANE_BYTES + (uint32_t)(r * 80 + ch * 16);
        size_t src = (size_t)(m0 + r) * 512 + kc + ch * 8;
        cpa16(d, (plane ? g_Xl : g_Xh) + src);
    }
    // B planes
#pragma unroll
    for (int i = 0; i < 4; ++i) {
        int cid = tid + i * 256;
        int plane = cid >> 9;
        int r     = (cid & 511) >> 2;
        int ch    = cid & 3;
        uint32_t d = sb + 2 * PLANE_BYTES + plane * PLANE_BYTES
                   + (uint32_t)(r * 80 + ch * 16);
        size_t src = (size_t)(n0 + r) * 512 + kc + ch * 8;
        cpa16(d, (plane ? Wl : Wh) + src);
    }
    asm volatile("cp.async.commit_group;\n" ::: "memory");
}

__global__ void __launch_bounds__(256, 1) gemm_kernel(int wsel)
{
    extern __shared__ char smem[];
    const uint32_t sbase = smem_u32(smem);
    const int tid = threadIdx.x;
    const int wid = tid >> 5;
    const int lane = tid & 31;
    const int g  = lane >> 2;
    const int tg = lane & 3;
    const int wm = wid & 3;          // 0..3 -> rows wm*32
    const int wn = wid >> 2;         // 0..1 -> cols wn*64
    const int m0 = (int)blockIdx.y * 128;
    const int n0 = (int)blockIdx.x * 128;
    const __nv_bfloat16* __restrict__ Wh = g_Wt[2 * wsel];
    const __nv_bfloat16* __restrict__ Wl = g_Wt[2 * wsel + 1];

    float acc[2][8][4];
#pragma unroll
    for (int mt = 0; mt < 2; ++mt)
#pragma unroll
        for (int nt = 0; nt < 8; ++nt)
#pragma unroll
            for (int i = 0; i < 4; ++i) acc[mt][nt][i] = 0.f;

    // prologue: stages 0,1,2
    g_load_stage(sbase + 0 * STG_BYTES, 0,  m0, n0, Wh, Wl, tid);
    g_load_stage(sbase + 1 * STG_BYTES, 32, m0, n0, Wh, Wl, tid);
    g_load_stage(sbase + 2 * STG_BYTES, 64, m0, n0, Wh, Wl, tid);

#pragma unroll 1
    for (int s = 0; s < 16; ++s) {
        asm volatile("cp.async.wait_group 2;\n" ::: "memory");
        __syncthreads();
        const uint32_t st = sbase + (uint32_t)(s % 3) * STG_BYTES;
        // base byte offsets for this warp's A rows / B rows
        const uint32_t aRow = st + (uint32_t)((wm * 32 + g) * 80 + tg * 4);
        const uint32_t bRow = st + 2 * PLANE_BYTES + (uint32_t)((wn * 64 + g) * 80 + tg * 4);
#pragma unroll
        for (int ks = 0; ks < 2; ++ks) {
            const uint32_t ko = (uint32_t)(ks * 32);  // 16 bf16 = 32 B
            uint32_t ah[2][4], al[2][4];
#pragma unroll
            for (int mt = 0; mt < 2; ++mt) {
                uint32_t base = aRow + (uint32_t)(mt * 16 * 80) + ko;
                asm volatile("ld.shared.b32 %0, [%1];"      : "=r"(ah[mt][0]) : "r"(base));
                asm volatile("ld.shared.b32 %0, [%1+640];"  : "=r"(ah[mt][1]) : "r"(base));
                asm volatile("ld.shared.b32 %0, [%1+16];"   : "=r"(ah[mt][2]) : "r"(base));
                asm volatile("ld.shared.b32 %0, [%1+656];"  : "=r"(ah[mt][3]) : "r"(base));
                uint32_t basel = base + PLANE_BYTES;
                asm volatile("ld.shared.b32 %0, [%1];"      : "=r"(al[mt][0]) : "r"(basel));
                asm volatile("ld.shared.b32 %0, [%1+640];"  : "=r"(al[mt][1]) : "r"(basel));
                asm volatile("ld.shared.b32 %0, [%1+16];"   : "=r"(al[mt][2]) : "r"(basel));
                asm volatile("ld.shared.b32 %0, [%1+656];"  : "=r"(al[mt][3]) : "r"(basel));
            }
#pragma unroll
            for (int nt = 0; nt < 8; ++nt) {
                uint32_t bbase = bRow + (uint32_t)(nt * 8 * 80) + ko;
                uint32_t bh[2], bl[2];
                asm volatile("ld.shared.b32 %0, [%1];"    : "=r"(bh[0]) : "r"(bbase));
                asm volatile("ld.shared.b32 %0, [%1+16];" : "=r"(bh[1]) : "r"(bbase));
                uint32_t bbl = bbase + PLANE_BYTES;
                asm volatile("ld.shared.b32 %0, [%1];"    : "=r"(bl[0]) : "r"(bbl));
                asm volatile("ld.shared.b32 %0, [%1+16];" : "=r"(bl[1]) : "r"(bbl));
#pragma unroll
                for (int mt = 0; mt < 2; ++mt) {
                    mma_bf16(acc[mt][nt], ah[mt], bh);
                    mma_bf16(acc[mt][nt], ah[mt], bl);
                    mma_bf16(acc[mt][nt], al[mt], bh);
                }
            }
        }
        __syncthreads();
        if (s + 3 < 16)
            g_load_stage(sbase + (uint32_t)(s % 3) * STG_BYTES, (s + 3) * 32,
                         m0, n0, Wh, Wl, tid);
    }

    // epilogue: D[row][col] mapping per PTX m16n8k16 lane layout
#pragma unroll
    for (int mt = 0; mt < 2; ++mt) {
        int r0 = m0 + wm * 32 + mt * 16 + g;
#pragma unroll
        for (int nt = 0; nt < 8; ++nt) {
            int c = n0 + wn * 64 + nt * 8 + tg * 2;
            *(float2*)&g_Y[(size_t)r0 * 512 + c]       = make_float2(acc[mt][nt][0], acc[mt][nt][1]);
            *(float2*)&g_Y[(size_t)(r0 + 8) * 512 + c] = make_float2(acc[mt][nt][2], acc[mt][nt][3]);
        }
    }
}

// ---------------- small kernels ---------------------------------------------
__global__ void __launch_bounds__(512) condw_kernel(
    const float* __restrict__ cond, const float* __restrict__ W0)
{
    __shared__ float sc[8 * 128];
    const int n  = threadIdx.x;
    const int bb = blockIdx.x * 8;
    for (int idx = n; idx < 8 * 128; idx += 512) sc[idx] = cond[bb * 128 + idx];
    __syncthreads();
    float acc[8];
#pragma unroll
    for (int j = 0; j < 8; ++j) acc[j] = 0.f;
    for (int c = 0; c < 128; ++c) {
        float w = W0[(4 + c) * 512 + n];
#pragma unroll
        for (int j = 0; j < 8; ++j) acc[j] = fmaf(sc[j * 128 + c], w, acc[j]);
    }
#pragma unroll
    for (int j = 0; j < 8; ++j) g_condW[(bb + j) * 512 + n] = acc[j];
}

// Wt[sel][n*512+k] = bf16 split of W[(2+k)*512+n]  (transposed, rows 2..513)
__global__ void __launch_bounds__(256) prep_kernel(
    const float* __restrict__ W1, const float* __restrict__ W2)
{
    int idx = blockIdx.x * 256 + threadIdx.x;   // 0..262143
    int n = idx >> 9, k = idx & 511;
    float v1 = W1[(2 + k) * 512 + n];
    __nv_bfloat16 h1 = __float2bfloat16_rn(v1);
    g_Wt[0][idx] = h1;
    g_Wt[1][idx] = __float2bfloat16_rn(v1 - __bfloat162float(h1));
    float v2 = W2[(2 + k) * 512 + n];
    __nv_bfloat16 h2 = __float2bfloat16_rn(v2);
    g_Wt[2][idx] = h2;
    g_Wt[3][idx] = __float2bfloat16_rn(v2 - __bfloat162float(h2));
}

__device__ __forceinline__ void wsplit(size_t o, float v) {
    __nv_bfloat16 h = __float2bfloat16_rn(v);
    g_Xh[o] = h;
    g_Xl[o] = __float2bfloat16_rn(v - __bfloat162float(h));
}

#define RED6()                                         \
    _Pragma("unroll")                                  \
    for (int o = 16; o > 0; o >>= 1) {                 \
        s1 += __shfl_xor_sync(0xffffffffu, s1, o);     \
        s2 += __shfl_xor_sync(0xffffffffu, s2, o);     \
        s3 += __shfl_xor_sync(0xffffffffu, s3, o);     \
        s4 += __shfl_xor_sync(0xffffffffu, s4, o);     \
        s5 += __shfl_xor_sync(0xffffffffu, s5, o);     \
        s6 += __shfl_xor_sync(0xffffffffu, s6, o);     \
    }

// layer0 (algebraic) + LN + softplus JVP -> X planes
__global__ void __launch_bounds__(256) ln0_kernel(
    const float* __restrict__ tptr, const float* __restrict__ z,
    const float* __restrict__ W0, const float* __restrict__ b0,
    const float* __restrict__ g0, const float* __restrict__ be0)
{
    const int l = threadIdx.x & 31;
    const int t = blockIdx.x * 8 + (threadIdx.x >> 5);
    const float tval = tptr[0];
    const float pos = (float)((t & 63) + 1) * (1.f / 64.f);
    const int batch = t >> 6;
    const float z0 = __ldg(&z[2 * t]), z1 = __ldg(&z[2 * t + 1]);

    float x[16], u0[16], u1[16];
    float s1 = 0.f, s2 = 0.f, s3 = 0.f, s4 = 0.f, s5 = 0.f, s6 = 0.f;
#pragma unroll
    for (int i = 0; i < 16; ++i) {
        int k = l + i * 32;
        float w2 = __ldg(&W0[1024 + k]);
        float w3 = __ldg(&W0[1536 + k]);
        float xv = tval * __ldg(&W0[k]) + pos * __ldg(&W0[512 + k])
                 + z0 * w2 + z1 * w3
                 + __ldg(&g_condW[batch * 512 + k]) + __ldg(&b0[k]);
        x[i] = xv; u0[i] = w2; u1[i] = w3;
        s1 += xv; s2 += xv * xv; s3 += w2; s4 += xv * w2; s5 += w3; s6 += xv * w3;
    }
    RED6();
    const float inv = 1.f / 512.f;
    float mu = s1 * inv, var = s2 * inv - mu * mu;
    float r = rsqrtf(var + EPS);
    float mu0 = s3 * inv, mu1 = s5 * inv;
    float r3c0 = r * r * r * (s4 * inv - mu * mu0);
    float r3c1 = r * r * r * (s6 * inv - mu * mu1);
#pragma unroll
    for (int i = 0; i < 16; ++i) {
        int k = l + i * 32;
        float xc = x[i] - mu;
        float gg = __ldg(&g0[k]);
        float y = fmaf(xc * r, gg, __ldg(&be0[k]));
        float e = __expf(-fabsf(y));
        float sp = fmaxf(y, 0.f) + log1pf(e);
        float sg = (y >= 0.f) ? (1.f / (1.f + e)) : (e / (1.f + e));
        float d0 = sg * gg * (r * (u0[i] - mu0) - xc * r3c0);
        float d1 = sg * gg * (r * (u1[i] - mu1) - xc * r3c1);
        wsplit((size_t)t * 512 + k, sp);
        wsplit((size_t)(NTOK + t) * 512 + k, d0);
        wsplit((size_t)(2 * NTOK + t) * 512 + k, d1);
    }
}

// LN on GEMM output Y (+ te/pos/bias), softplus JVP -> X planes
__global__ void __launch_bounds__(256) ln_mid_kernel(
    const float* __restrict__ tptr, const float* __restrict__ bv,
    const float* __restrict__ gv, const float* __restrict__ bev,
    const float* __restrict__ Wfull)
{
    const int l = threadIdx.x & 31;
    const int t = blockIdx.x * 8 + (threadIdx.x >> 5);
    const float tval = tptr[0];
    const float pos = (float)((t & 63) + 1) * (1.f / 64.f);

    float x[16], u0[16], u1[16];
    float s1 = 0.f, s2 = 0.f, s3 = 0.f, s4 = 0.f, s5 = 0.f, s6 = 0.f;
#pragma unroll
    for (int i = 0; i < 16; ++i) {
        int k = l + i * 32;
        float xv = g_Y[(size_t)t * 512 + k]
                 + __ldg(&bv[k]) + tval * __ldg(&Wfull[k]) + pos * __ldg(&Wfull[512 + k]);
        float a = g_Y[(size_t)(NTOK + t) * 512 + k];
        float b = g_Y[(size_t)(2 * NTOK + t) * 512 + k];
        x[i] = xv; u0[i] = a; u1[i] = b;
        s1 += xv; s2 += xv * xv; s3 += a; s4 += xv * a; s5 += b; s6 += xv * b;
    }
    RED6();
    const float inv = 1.f / 512.f;
    float mu = s1 * inv, var = s2 * inv - mu * mu;
    float r = rsqrtf(var + EPS);
    float mu0 = s3 * inv, mu1 = s5 * inv;
    float r3c0 = r * r * r * (s4 * inv - mu * mu0);
    float r3c1 = r * r * r * (s6 * inv - mu * mu1);
#pragma unroll
    for (int i = 0; i < 16; ++i) {
        int k = l + i * 32;
        float xc = x[i] - mu;
        float gg = __ldg(&gv[k]);
        float y = fmaf(xc * r, gg, __ldg(&bev[k]));
        float e = __expf(-fabsf(y));
        float sp = fmaxf(y, 0.f) + log1pf(e);
        float sg = (y >= 0.f) ? (1.f / (1.f + e)) : (e / (1.f + e));
        float d0 = sg * gg * (r * (u0[i] - mu0) - xc * r3c0);
        float d1 = sg * gg * (r * (u1[i] - mu1) - xc * r3c1);
        wsplit((size_t)t * 512 + k, sp);
        wsplit((size_t)(NTOK + t) * 512 + k, d0);
        wsplit((size_t)(2 * NTOK + t) * 512 + k, d1);
    }
}

// LN2 on Y + layer-3 dots -> out
__global__ void __launch_bounds__(256) final_kernel(
    const float* __restrict__ tptr, const float* __restrict__ bv,
    const float* __restrict__ gv, const float* __restrict__ bev,
    const float* __restrict__ Wfull, const float* __restrict__ W3,
    const float* __restrict__ b3, float* __restrict__ out)
{
    const int l = threadIdx.x & 31;
    const int t = blockIdx.x * 8 + (threadIdx.x >> 5);
    const float tval = tptr[0];
    const float pos = (float)((t & 63) + 1) * (1.f / 64.f);

    float x[16], u0[16], u1[16];
    float s1 = 0.f, s2 = 0.f, s3 = 0.f, s4 = 0.f, s5 = 0.f, s6 = 0.f;
#pragma unroll
    for (int i = 0; i < 16; ++i) {
        int k = l + i * 32;
        float xv = g_Y[(size_t)t * 512 + k]
                 + __ldg(&bv[k]) + tval * __ldg(&Wfull[k]) + pos * __ldg(&Wfull[512 + k]);
        float a = g_Y[(size_t)(NTOK + t) * 512 + k];
        float b = g_Y[(size_t)(2 * NTOK + t) * 512 + k];
        x[i] = xv; u0[i] = a; u1[i] = b;
        s1 += xv; s2 += xv * xv; s3 += a; s4 += xv * a; s5 += b; s6 += xv * b;
    }
    RED6();
    const float inv = 1.f / 512.f;
    float mu = s1 * inv, var = s2 * inv - mu * mu;
    float r = rsqrtf(var + EPS);
    float mu0 = s3 * inv, mu1 = s5 * inv;
    float r3c0 = r * r * r * (s4 * inv - mu * mu0);
    float r3c1 = r * r * r * (s6 * inv - mu * mu1);

    float a0 = 0.f, a1 = 0.f, d0s = 0.f, d1s = 0.f;
#pragma unroll
    for (int i = 0; i < 16; ++i) {
        int k = l + i * 32;
        float xc = x[i] - mu;
        float gg = __ldg(&gv[k]);
        float y = fmaf(xc * r, gg, __ldg(&bev[k]));
        float e = __expf(-fabsf(y));
        float sp = fmaxf(y, 0.f) + log1pf(e);
        float sg = (y >= 0.f) ? (1.f / (1.f + e)) : (e / (1.f + e));
        float d0 = sg * gg * (r * (u0[i] - mu0) - xc * r3c0);
        float d1 = sg * gg * (r * (u1[i] - mu1) - xc * r3c1);
        float2 wv = *(const float2*)&W3[(2 + k) * 2];
        a0 = fmaf(sp, wv.x, a0);
        a1 = fmaf(sp, wv.y, a1);
        d0s = fmaf(d0, wv.x, d0s);
        d1s = fmaf(d1, wv.y, d1s);
    }
#pragma unroll
    for (int o = 16; o > 0; o >>= 1) {
        a0  += __shfl_xor_sync(0xffffffffu, a0, o);
        a1  += __shfl_xor_sync(0xffffffffu, a1, o);
        d0s += __shfl_xor_sync(0xffffffffu, d0s, o);
        d1s += __shfl_xor_sync(0xffffffffu, d1s, o);
    }
    if (l == 0) {
        out[t * 2 + 0] = a0 + b3[0] + tval * W3[0] + pos * W3[2];
        out[t * 2 + 1] = a1 + b3[1] + tval * W3[1] + pos * W3[3];
        out[2 * NTOK + t] = -(d0s + d1s);
    }
}

// ---------------- host ------------------------------------------------------
extern "C" void kernel_launch(void* const* d_in, const int* in_sizes, int n_in,
                              void* d_out, int out_size)
{
    const float* t    = (const float*)d_in[0];
    const float* z    = (const float*)d_in[1];
    const float* cond = (const float*)d_in[2];
    const float* W0   = (const float*)d_in[3];
    const float* b0   = (const float*)d_in[4];
    const float* g0   = (const float*)d_in[5];
    const float* be0  = (const float*)d_in[6];
    const float* W1   = (const float*)d_in[7];
    const float* b1   = (const float*)d_in[8];
    const float* g1   = (const float*)d_in[9];
    const float* be1  = (const float*)d_in[10];
    const float* W2   = (const float*)d_in[11];
    const float* b2   = (const float*)d_in[12];
    const float* g2   = (const float*)d_in[13];
    const float* be2  = (const float*)d_in[14];
    const float* W3   = (const float*)d_in[15];
    const float* b3   = (const float*)d_in[16];
    float* out = (float*)d_out;

    const int gemm_smem = 3 * STG_BYTES;   // 122880 B
    cudaFuncSetAttribute(gemm_kernel, cudaFuncAttributeMaxDynamicSharedMemorySize,
                         gemm_smem);

    dim3 ggrid(4, ROWS / 128);             // N-tiles fastest -> A reuse in L2

    condw_kernel<<<256, 512>>>(cond, W0);
    prep_kernel<<<1024, 256>>>(W1, W2);
    ln0_kernel<<<NTOK / 8, 256>>>(t, z, W0, b0, g0, be0);
    gemm_kernel<<<ggrid, 256, gemm_smem>>>(0);
    ln_mid_kernel<<<NTOK / 8, 256>>>(t, b1, g1, be1, W1);
    gemm_kernel<<<ggrid, 256, gemm_smem>>>(1);
    final_kernel<<<NTOK / 8, 256>>>(t, b2, g2, be2, W2, W3, b3, out);
}